// round 10
// baseline (speedup 1.0000x reference)
#include <cuda_runtime.h>
#include <cuda_bf16.h>
#include <cstdint>

// ---------------- problem constants ----------------
constexpr int IN_F  = 4096;
constexpr int OUT_F = 4096;
constexpr int M_TOT = 8192;
constexpr int NB    = (OUT_F / 16) * (IN_F / 16);   // 65536 tiles

// ---------------- GEMM tiling ----------------
constexpr int BM = 128;
constexpr int BN = 256;
constexpr int BK = 32;
constexpr int STAGES = 3;
constexpr int NK = IN_F / BK;                   // 128 k-iterations
constexpr int ROWPAD = 40;                      // floats per smem row (conflict-free v2)
constexpr int A_TILE_FLOATS = BM * ROWPAD;      // 5120
constexpr int B_TILE_FLOATS = BN * ROWPAD;      // 10240
constexpr int STAGE_FLOATS  = A_TILE_FLOATS + B_TILE_FLOATS;   // 15360
constexpr int SMEM_TOTAL    = STAGES * STAGE_FLOATS * 4;       // 184320 bytes

// ---------------- scratch (k-interleaved layout: within each 8-k group,
// logical k order stored as [0,4,1,5,2,6,3,7]) ----------------
__device__ float g_x[(size_t)M_TOT * IN_F];
__device__ float g_W[(size_t)OUT_F * IN_F];

// ---------------- helpers ----------------
__device__ __forceinline__ float to_tf32_rn(float x) {
    uint32_t r;
    asm("cvt.rna.tf32.f32 %0, %1;" : "=r"(r) : "f"(x));
    return __uint_as_float(r);
}
__device__ __forceinline__ uint32_t smem_to_u32(const void* p) {
    uint32_t a;
    asm("{ .reg .u64 t; cvta.to.shared.u64 t, %1; cvt.u32.u64 %0, t; }" : "=r"(a) : "l"(p));
    return a;
}
__device__ __forceinline__ void cp_async16(uint32_t dst, const void* src) {
    asm volatile("cp.async.cg.shared.global [%0], [%1], 16;" :: "r"(dst), "l"(src) : "memory");
}
#define CP_COMMIT() asm volatile("cp.async.commit_group;" ::: "memory")
#define CP_WAIT1()  asm volatile("cp.async.wait_group 1;" ::: "memory")

__device__ __forceinline__ void mma_tf32(float* c, const uint32_t* a, const uint32_t* b) {
    asm volatile(
        "mma.sync.aligned.m16n8k8.row.col.f32.tf32.tf32.f32 "
        "{%0,%1,%2,%3}, {%4,%5,%6,%7}, {%8,%9}, {%0,%1,%2,%3};"
        : "+f"(c[0]), "+f"(c[1]), "+f"(c[2]), "+f"(c[3])
        : "r"(a[0]), "r"(a[1]), "r"(a[2]), "r"(a[3]), "r"(b[0]), "r"(b[1]));
}

// ---------------------------------------------------------------------------
// Kernel 1: per-128 FWHT, output rounded to tf32 grid, stored k-interleaved.
// Even/odd lane pairs exchange halves via shfl so float4 stores survive.
// ---------------------------------------------------------------------------
__global__ void __launch_bounds__(256) fwht_kernel(const float* __restrict__ in,
                                                   float* __restrict__ out) {
    const int warp = (blockIdx.x << 3) | (threadIdx.x >> 5);
    const int lane = threadIdx.x & 31;
    const size_t base = (size_t)warp * 128;

    float4 v = reinterpret_cast<const float4*>(in + base)[lane];
    float a = v.x, b = v.y, c = v.z, d = v.w, t;
    t = a; a = a + b; b = t - b;
    t = c; c = c + d; d = t - d;
    t = a; a = a + c; c = t - c;
    t = b; b = b + d; d = t - d;
    #pragma unroll
    for (int mask = 1; mask <= 16; mask <<= 1) {
        float oa = __shfl_xor_sync(0xFFFFFFFFu, a, mask);
        float ob = __shfl_xor_sync(0xFFFFFFFFu, b, mask);
        float oc = __shfl_xor_sync(0xFFFFFFFFu, c, mask);
        float od = __shfl_xor_sync(0xFFFFFFFFu, d, mask);
        const bool hi = (lane & mask) != 0;
        a = hi ? (oa - a) : (a + oa);
        b = hi ? (ob - b) : (b + ob);
        c = hi ? (oc - c) : (c + oc);
        d = hi ? (od - d) : (d + od);
    }
    const float s = 0.08838834764831845f;
    a = to_tf32_rn(a * s); b = to_tf32_rn(b * s);
    c = to_tf32_rn(c * s); d = to_tf32_rn(d * s);

    // k-interleave within each 8-group: lane pair (2g, 2g+1) holds logical
    // k 0..7 of group g; storage order [e.a, o.a, e.b, o.b, e.c, o.c, e.d, o.d]
    const float sa = __shfl_xor_sync(0xFFFFFFFFu, a, 1);
    const float sb = __shfl_xor_sync(0xFFFFFFFFu, b, 1);
    const float sc = __shfl_xor_sync(0xFFFFFFFFu, c, 1);
    const float sd = __shfl_xor_sync(0xFFFFFFFFu, d, 1);
    float4 o = (lane & 1) ? make_float4(sc, c, sd, d)
                          : make_float4(a, sa, b, sb);
    reinterpret_cast<float4*>(out + base)[lane] = o;
}

// ---------------------------------------------------------------------------
// Kernel 2: trellis decode, tf32-rounded, stored k-interleaved.
// ---------------------------------------------------------------------------
__global__ void __launch_bounds__(256) decode_kernel(const int* __restrict__ trellis,
                                                     const float* __restrict__ tlut,
                                                     const float* __restrict__ scales,
                                                     float* __restrict__ W) {
    const int nb = blockIdx.x;
    const int t  = threadIdx.x;

    __shared__ uint32_t w[32];
    if (t < 32) w[t] = (uint32_t)trellis[nb * 32 + t] & 0xFFFFu;
    __syncthreads();

    const int p   = t << 1;
    const int i   = p >> 4;
    const int off = p & 15;
    const uint32_t s = (w[i] << 16) | w[(i + 1) & 31];
    const uint32_t state = (s >> (16 - off)) & 0xFFFFu;

    const float val = tlut[state];

    const int rb = nb >> 8;
    const int cb = nb & 255;
    const int tx = t >> 4;
    const int ty = t & 15;
    const int row = rb * 16 + tx;
    const int col = cb * 16 + ty;

    const float sc = scales[row * (IN_F / 128) + (col >> 7)];
    // k-interleave: within 8-group, pos = 2*(w&3) + (w>>2)
    const int wg = col & 7;
    const int colstore = (col & ~7) | ((wg & 3) << 1) | (wg >> 2);
    W[(size_t)row * IN_F + colstore] = to_tf32_rn(val * sc);
}

// ---------------------------------------------------------------------------
// Kernel 3: tf32 mma.sync GEMM  C[M,N] = A[M,K] @ B[N,K]^T
// 128x256 CTA tile, BK=32, 3-stage cp.async pipeline, 8 warps x (64x64).
// Operands are k-interleaved -> all fragment loads are ld.shared.v2.
// ---------------------------------------------------------------------------
__global__ void __launch_bounds__(256, 1) gemm_mma_kernel(const float* __restrict__ A,
                                                          const float* __restrict__ B,
                                                          float* __restrict__ C) {
    extern __shared__ float smem[];
    const uint32_t sbase = smem_to_u32(smem);

    const int tid  = threadIdx.x;
    const int lane = tid & 31;
    const int warp = tid >> 5;
    const int warp_m = warp >> 2;          // 0..1  -> 64-row slice
    const int warp_n = warp & 3;           // 0..3  -> 64-col slice

    // swizzle: supertiles of 8 m-blocks x 16 n-blocks (~1 wave each)
    const int bid = blockIdx.x;
    const int sm_ = bid >> 7;              // 0..7
    const int w_  = bid & 127;
    const int bm  = ((sm_ << 3) | (w_ & 7)) * BM;
    const int bn  = (w_ >> 3) * BN;

    // global->smem: 16B chunks
    const int lrow = tid >> 3;             // 0..31
    const int lcol = (tid & 7) << 2;       // 0,4,...,28

    const float* Ag = A + (size_t)(bm + lrow) * IN_F + lcol;
    const float* Bg = B + (size_t)(bn + lrow) * IN_F + lcol;

    auto load_stage = [&](int buf, int kt) {
        const uint32_t sA = sbase + (uint32_t)(buf * STAGE_FLOATS) * 4;
        const uint32_t sB = sA + (uint32_t)A_TILE_FLOATS * 4;
        const int koff = kt * BK;
        #pragma unroll
        for (int r = 0; r < 4; r++)
            cp_async16(sA + (uint32_t)((lrow + (r << 5)) * ROWPAD + lcol) * 4,
                       Ag + (size_t)(r << 5) * IN_F + koff);
        #pragma unroll
        for (int r = 0; r < 8; r++)
            cp_async16(sB + (uint32_t)((lrow + (r << 5)) * ROWPAD + lcol) * 4,
                       Bg + (size_t)(r << 5) * IN_F + koff);
    };

    float acc[4][8][4];
    #pragma unroll
    for (int i = 0; i < 4; i++)
        #pragma unroll
        for (int j = 0; j < 8; j++)
            #pragma unroll
            for (int r = 0; r < 4; r++) acc[i][j][r] = 0.0f;

    #pragma unroll
    for (int s = 0; s < STAGES - 1; s++) {
        load_stage(s, s);
        CP_COMMIT();
    }

    const int lq = lane >> 2;              // 0..7
    const int lr = lane & 3;               // 0..3

    for (int kt = 0; kt < NK; kt++) {
        CP_WAIT1();
        __syncthreads();

        if (kt + STAGES - 1 < NK) load_stage((kt + STAGES - 1) % STAGES, kt + STAGES - 1);
        CP_COMMIT();

        const int buf = kt % STAGES;
        const float* As = smem + buf * STAGE_FLOATS;
        const float* Bs = As + A_TILE_FLOATS;
        const float* Aw = As + (warp_m * 64 + lq) * ROWPAD + 2 * lr;
        const float* Bw = Bs + (warp_n * 64 + lq) * ROWPAD + 2 * lr;

        #pragma unroll
        for (int ks = 0; ks < 4; ks++) {
            const int k0 = ks << 3;
            uint32_t af[4][4], bf[8][2];
            #pragma unroll
            for (int mt = 0; mt < 4; mt++) {
                float2 lo = *reinterpret_cast<const float2*>(Aw + (mt * 16) * ROWPAD + k0);
                float2 hi = *reinterpret_cast<const float2*>(Aw + (mt * 16 + 8) * ROWPAD + k0);
                af[mt][0] = __float_as_uint(lo.x);   // (row lq,   k lr)
                af[mt][1] = __float_as_uint(hi.x);   // (row lq+8, k lr)
                af[mt][2] = __float_as_uint(lo.y);   // (row lq,   k lr+4)
                af[mt][3] = __float_as_uint(hi.y);   // (row lq+8, k lr+4)
            }
            #pragma unroll
            for (int nt = 0; nt < 8; nt++) {
                float2 b = *reinterpret_cast<const float2*>(Bw + (nt * 8) * ROWPAD + k0);
                bf[nt][0] = __float_as_uint(b.x);
                bf[nt][1] = __float_as_uint(b.y);
            }
            #pragma unroll
            for (int mt = 0; mt < 4; mt++)
                #pragma unroll
                for (int nt = 0; nt < 8; nt++)
                    mma_tf32(acc[mt][nt], af[mt], bf[nt]);
        }
    }

    // epilogue
    const int crow = bm + warp_m * 64 + lq;
    const int ccol = bn + warp_n * 64 + 2 * lr;
    #pragma unroll
    for (int mt = 0; mt < 4; mt++) {
        #pragma unroll
        for (int nt = 0; nt < 8; nt++) {
            float* p0 = C + (size_t)(crow + mt * 16) * OUT_F + ccol + nt * 8;
            float* p1 = p0 + (size_t)8 * OUT_F;
            *reinterpret_cast<float2*>(p0) = make_float2(acc[mt][nt][0], acc[mt][nt][1]);
            *reinterpret_cast<float2*>(p1) = make_float2(acc[mt][nt][2], acc[mt][nt][3]);
        }
    }
}

// ---------------------------------------------------------------------------
extern "C" void kernel_launch(void* const* d_in, const int* in_sizes, int n_in,
                              void* d_out, int out_size) {
    const float* input   = (const float*)d_in[0];
    const int*   trellis = (const int*)  d_in[1];
    const float* tlut    = (const float*)d_in[2];
    const float* scales  = (const float*)d_in[3];
    float*       out     = (float*)d_out;

    float* xbuf; float* wbuf;
    cudaGetSymbolAddress((void**)&xbuf, g_x);
    cudaGetSymbolAddress((void**)&wbuf, g_W);

    // 1) Hadamard rotate activations
    fwht_kernel<<<(M_TOT * (IN_F / 128)) / 8, 256>>>(input, xbuf);
    // 2) Decode weights
    decode_kernel<<<NB, 256>>>(trellis, tlut, scales, wbuf);
    // 3) tf32 mma.sync GEMM
    static bool attr_set = false;
    if (!attr_set) {
        cudaFuncSetAttribute(gemm_mma_kernel,
                             cudaFuncAttributeMaxDynamicSharedMemorySize, SMEM_TOTAL);
        attr_set = true;
    }
    const int nblocks = (M_TOT / BM) * (OUT_F / BN);   // 1024
    gemm_mma_kernel<<<nblocks, 256, SMEM_TOTAL>>>(xbuf, wbuf, out);
}

// round 11
// speedup vs baseline: 1.8578x; 1.8578x over previous
#include <cuda_runtime.h>
#include <cuda_fp16.h>
#include <cstdint>

// ---------------- problem constants ----------------
constexpr int IN_F  = 4096;
constexpr int OUT_F = 4096;
constexpr int M_TOT = 8192;
constexpr int NB    = (OUT_F / 16) * (IN_F / 16);   // 65536 tiles

// ---------------- GEMM tiling ----------------
constexpr int BM = 128;
constexpr int BN = 256;
constexpr int BK = 64;                   // halfs of K per pipeline stage
constexpr int STAGES = 3;
constexpr int NKT = IN_F / BK;           // 64 k-iterations
constexpr int P = 80;                    // halfs per smem row (64 data + 16 pad)
constexpr int A_TILE_HALFS = BM * P;     // 10240
constexpr int B_TILE_HALFS = BN * P;     // 20480
constexpr int STAGE_HALFS  = A_TILE_HALFS + B_TILE_HALFS;    // 30720
constexpr int SMEM_TOTAL   = STAGES * STAGE_HALFS * 2;       // 184320 bytes

// ---------------- scratch (fp16, k-interleaved per 16-k group:
// storage[4r+{0,1,2,3}] = logical k {2r, 2r+1, 2r+8, 2r+9}) ----------------
__device__ __half g_x[(size_t)M_TOT * IN_F];
__device__ __half g_W[(size_t)OUT_F * IN_F];

// ---------------- helpers ----------------
__device__ __forceinline__ uint32_t smem_to_u32(const void* p) {
    uint32_t a;
    asm("{ .reg .u64 t; cvta.to.shared.u64 t, %1; cvt.u32.u64 %0, t; }" : "=r"(a) : "l"(p));
    return a;
}
__device__ __forceinline__ void cp_async16(uint32_t dst, const void* src) {
    asm volatile("cp.async.cg.shared.global [%0], [%1], 16;" :: "r"(dst), "l"(src) : "memory");
}
#define CP_COMMIT() asm volatile("cp.async.commit_group;" ::: "memory")
#define CP_WAIT1()  asm volatile("cp.async.wait_group 1;" ::: "memory")

__device__ __forceinline__ void mma_f16(float* c, const uint32_t* a, const uint32_t* b) {
    asm volatile(
        "mma.sync.aligned.m16n8k16.row.col.f32.f16.f16.f32 "
        "{%0,%1,%2,%3}, {%4,%5,%6,%7}, {%8,%9}, {%0,%1,%2,%3};"
        : "+f"(c[0]), "+f"(c[1]), "+f"(c[2]), "+f"(c[3])
        : "r"(a[0]), "r"(a[1]), "r"(a[2]), "r"(a[3]), "r"(b[0]), "r"(b[1]));
}

// ---------------------------------------------------------------------------
// Kernel 1: per-128 FWHT -> fp16, stored k-interleaved.
// Lane l holds outputs k = 4l..4l+3 of its 128-group.
// ---------------------------------------------------------------------------
__global__ void __launch_bounds__(256) fwht_kernel(const float* __restrict__ in,
                                                   __half* __restrict__ out) {
    const int warp = (blockIdx.x << 3) | (threadIdx.x >> 5);
    const int lane = threadIdx.x & 31;
    const size_t base = (size_t)warp * 128;

    float4 v = reinterpret_cast<const float4*>(in + base)[lane];
    float a = v.x, b = v.y, c = v.z, d = v.w, t;
    t = a; a = a + b; b = t - b;
    t = c; c = c + d; d = t - d;
    t = a; a = a + c; c = t - c;
    t = b; b = b + d; d = t - d;
    #pragma unroll
    for (int mask = 1; mask <= 16; mask <<= 1) {
        float oa = __shfl_xor_sync(0xFFFFFFFFu, a, mask);
        float ob = __shfl_xor_sync(0xFFFFFFFFu, b, mask);
        float oc = __shfl_xor_sync(0xFFFFFFFFu, c, mask);
        float od = __shfl_xor_sync(0xFFFFFFFFu, d, mask);
        const bool hi = (lane & mask) != 0;
        a = hi ? (oa - a) : (a + oa);
        b = hi ? (ob - b) : (b + ob);
        c = hi ? (oc - c) : (c + oc);
        d = hi ? (od - d) : (d + od);
    }
    const float s = 0.08838834764831845f;
    __half2 h01 = __floats2half2_rn(a * s, b * s);
    __half2 h23 = __floats2half2_rn(c * s, d * s);

    // interleave positions: q = supergroup (16-k), g = pair-in-supergroup
    const int q = lane >> 2;
    const int g = (lane >> 1) & 1;
    const int off = 16 * q + 2 * g + ((lane & 1) ? 8 : 0);   // half offset of (a,b)
    __half2* o2 = reinterpret_cast<__half2*>(out + base);
    o2[off >> 1]       = h01;    // positions off, off+1
    o2[(off >> 1) + 2] = h23;    // positions off+4, off+5
}

// ---------------------------------------------------------------------------
// Kernel 2: trellis decode -> fp16, stored k-interleaved.
// ---------------------------------------------------------------------------
__global__ void __launch_bounds__(256) decode_kernel(const int* __restrict__ trellis,
                                                     const float* __restrict__ tlut,
                                                     const float* __restrict__ scales,
                                                     __half* __restrict__ W) {
    const int nb = blockIdx.x;
    const int t  = threadIdx.x;

    __shared__ uint32_t w[32];
    if (t < 32) w[t] = (uint32_t)trellis[nb * 32 + t] & 0xFFFFu;
    __syncthreads();

    const int p   = t << 1;
    const int i   = p >> 4;
    const int off = p & 15;
    const uint32_t s = (w[i] << 16) | w[(i + 1) & 31];
    const uint32_t state = (s >> (16 - off)) & 0xFFFFu;

    const float val = tlut[state];

    const int rb = nb >> 8;
    const int cb = nb & 255;
    const int tx = t >> 4;
    const int ty = t & 15;
    const int row = rb * 16 + tx;
    const int col = cb * 16 + ty;

    const float sc = scales[row * (IN_F / 128) + (col >> 7)];
    // interleave within 16-k group: pos = 4*((k&7)>>1) + 2*(k>>3) + (k&1)
    const int k = col & 15;
    const int pos = 4 * ((k & 7) >> 1) + ((k >> 3) << 1) + (k & 1);
    const int colstore = (col & ~15) | pos;
    W[(size_t)row * IN_F + colstore] = __float2half_rn(val * sc);
}

// ---------------------------------------------------------------------------
// Kernel 3: fp16 mma.sync GEMM  C[M,N] = A[M,K] @ B[N,K]^T  (fp32 accum)
// 128x256 CTA tile, BK=64, 3-stage cp.async pipeline, 8 warps x (64x64).
// ---------------------------------------------------------------------------
__global__ void __launch_bounds__(256, 1) gemm_mma_kernel(const __half* __restrict__ A,
                                                          const __half* __restrict__ B,
                                                          float* __restrict__ C) {
    extern __shared__ __half smem[];
    const uint32_t sbase = smem_to_u32(smem);

    const int tid  = threadIdx.x;
    const int lane = tid & 31;
    const int warp = tid >> 5;
    const int warp_m = warp >> 2;          // 0..1  -> 64-row slice
    const int warp_n = warp & 3;           // 0..3  -> 64-col slice

    // swizzle: supertiles of 8 m-blocks x 16 n-blocks
    const int bid = blockIdx.x;
    const int sm_ = bid >> 7;
    const int w_  = bid & 127;
    const int bm  = ((sm_ << 3) | (w_ & 7)) * BM;
    const int bn  = (w_ >> 3) * BN;

    // global->smem: 16B (8-half) chunks; row stride P halfs in smem
    const int lrow   = tid >> 3;           // 0..31
    const int lchunk = (tid & 7) << 3;     // half offset 0,8,...,56

    const __half* Ag = A + (size_t)(bm + lrow) * IN_F + lchunk;
    const __half* Bg = B + (size_t)(bn + lrow) * IN_F + lchunk;

    auto load_stage = [&](int buf, int kt) {
        const uint32_t sA = sbase + (uint32_t)(buf * STAGE_HALFS) * 2;
        const uint32_t sB = sA + (uint32_t)A_TILE_HALFS * 2;
        const int koff = kt * BK;
        #pragma unroll
        for (int r = 0; r < 4; r++)
            cp_async16(sA + (uint32_t)((lrow + (r << 5)) * P + lchunk) * 2,
                       Ag + (size_t)(r << 5) * IN_F + koff);
        #pragma unroll
        for (int r = 0; r < 8; r++)
            cp_async16(sB + (uint32_t)((lrow + (r << 5)) * P + lchunk) * 2,
                       Bg + (size_t)(r << 5) * IN_F + koff);
    };

    float acc[4][8][4];
    #pragma unroll
    for (int i = 0; i < 4; i++)
        #pragma unroll
        for (int j = 0; j < 8; j++)
            #pragma unroll
            for (int r = 0; r < 4; r++) acc[i][j][r] = 0.0f;

    #pragma unroll
    for (int s = 0; s < STAGES - 1; s++) {
        load_stage(s, s);
        CP_COMMIT();
    }

    const int lq = lane >> 2;              // 0..7
    const int lr = lane & 3;               // 0..3

    for (int kt = 0; kt < NKT; kt++) {
        CP_WAIT1();
        __syncthreads();

        if (kt + STAGES - 1 < NKT) load_stage((kt + STAGES - 1) % STAGES, kt + STAGES - 1);
        CP_COMMIT();

        const int buf = kt % STAGES;
        const __half* As = smem + buf * STAGE_HALFS;
        const __half* Bs = As + A_TILE_HALFS;
        // fragment base: row (lq), half-offset 4*lr inside each 16-k supergroup
        const __half* Aw = As + (warp_m * 64 + lq) * P + 4 * lr;
        const __half* Bw = Bs + (warp_n * 64 + lq) * P + 4 * lr;

        #pragma unroll
        for (int ksp = 0; ksp < 4; ksp++) {    // 4 supergroups of 16 k
            const int k0 = ksp << 4;
            uint32_t af[4][4], bf[8][2];
            #pragma unroll
            for (int mt = 0; mt < 4; mt++) {
                uint2 lo = *reinterpret_cast<const uint2*>(Aw + (mt * 16) * P + k0);
                uint2 hi = *reinterpret_cast<const uint2*>(Aw + (mt * 16 + 8) * P + k0);
                af[mt][0] = lo.x;   // row lq,   k (2lr,2lr+1)
                af[mt][1] = hi.x;   // row lq+8, k (2lr,2lr+1)
                af[mt][2] = lo.y;   // row lq,   k (2lr+8,2lr+9)
                af[mt][3] = hi.y;   // row lq+8, k (2lr+8,2lr+9)
            }
            #pragma unroll
            for (int nt = 0; nt < 8; nt++) {
                uint2 b = *reinterpret_cast<const uint2*>(Bw + (nt * 8) * P + k0);
                bf[nt][0] = b.x;
                bf[nt][1] = b.y;
            }
            #pragma unroll
            for (int mt = 0; mt < 4; mt++)
                #pragma unroll
                for (int nt = 0; nt < 8; nt++)
                    mma_f16(acc[mt][nt], af[mt], bf[nt]);
        }
    }

    // epilogue
    const int crow = bm + warp_m * 64 + lq;
    const int ccol = bn + warp_n * 64 + 2 * lr;
    #pragma unroll
    for (int mt = 0; mt < 4; mt++) {
        #pragma unroll
        for (int nt = 0; nt < 8; nt++) {
            float* p0 = C + (size_t)(crow + mt * 16) * OUT_F + ccol + nt * 8;
            float* p1 = p0 + (size_t)8 * OUT_F;
            *reinterpret_cast<float2*>(p0) = make_float2(acc[mt][nt][0], acc[mt][nt][1]);
            *reinterpret_cast<float2*>(p1) = make_float2(acc[mt][nt][2], acc[mt][nt][3]);
        }
    }
}

// ---------------------------------------------------------------------------
extern "C" void kernel_launch(void* const* d_in, const int* in_sizes, int n_in,
                              void* d_out, int out_size) {
    const float* input   = (const float*)d_in[0];
    const int*   trellis = (const int*)  d_in[1];
    const float* tlut    = (const float*)d_in[2];
    const float* scales  = (const float*)d_in[3];
    float*       out     = (float*)d_out;

    __half* xbuf; __half* wbuf;
    cudaGetSymbolAddress((void**)&xbuf, g_x);
    cudaGetSymbolAddress((void**)&wbuf, g_W);

    // 1) Hadamard rotate activations -> fp16 (k-interleaved)
    fwht_kernel<<<(M_TOT * (IN_F / 128)) / 8, 256>>>(input, xbuf);
    // 2) Decode weights -> fp16 (k-interleaved)
    decode_kernel<<<NB, 256>>>(trellis, tlut, scales, wbuf);
    // 3) fp16 mma.sync GEMM (fp32 accumulate)
    static bool attr_set = false;
    if (!attr_set) {
        cudaFuncSetAttribute(gemm_mma_kernel,
                             cudaFuncAttributeMaxDynamicSharedMemorySize, SMEM_TOTAL);
        attr_set = true;
    }
    const int nblocks = (M_TOT / BM) * (OUT_F / BN);   // 1024
    gemm_mma_kernel<<<nblocks, 256, SMEM_TOTAL>>>(xbuf, wbuf, out);
}

// round 12
// speedup vs baseline: 1.9420x; 1.0453x over previous
#include <cuda_runtime.h>
#include <cuda_fp16.h>
#include <cstdint>

// ---------------- problem constants ----------------
constexpr int IN_F  = 4096;
constexpr int OUT_F = 4096;
constexpr int M_TOT = 8192;
constexpr int NB    = (OUT_F / 16) * (IN_F / 16);   // 65536 tiles

// ---------------- GEMM tiling ----------------
constexpr int BM = 128;
constexpr int BN = 256;
constexpr int BK = 64;                   // halfs of K per pipeline stage
constexpr int STAGES = 3;
constexpr int NKT = IN_F / BK;           // 64 k-iterations
constexpr int P = 80;                    // halfs per smem row (64 data + 16 pad)
constexpr int A_TILE_HALFS = BM * P;     // 10240
constexpr int B_TILE_HALFS = BN * P;     // 20480
constexpr int STAGE_HALFS  = A_TILE_HALFS + B_TILE_HALFS;    // 30720
constexpr int SMEM_TOTAL   = STAGES * STAGE_HALFS * 2;       // 184320 bytes

// ---------------- scratch (fp16, k-interleaved per 16-k group:
// storage[4r+{0,1,2,3}] = logical k {2r, 2r+1, 2r+8, 2r+9}) ----------------
__device__ __half g_x[(size_t)M_TOT * IN_F];
__device__ __half g_W[(size_t)OUT_F * IN_F];

// ---------------- helpers ----------------
__device__ __forceinline__ uint32_t smem_to_u32(const void* p) {
    uint32_t a;
    asm("{ .reg .u64 t; cvta.to.shared.u64 t, %1; cvt.u32.u64 %0, t; }" : "=r"(a) : "l"(p));
    return a;
}
__device__ __forceinline__ void cp_async16(uint32_t dst, const void* src) {
    asm volatile("cp.async.cg.shared.global [%0], [%1], 16;" :: "r"(dst), "l"(src) : "memory");
}
#define CP_COMMIT() asm volatile("cp.async.commit_group;" ::: "memory")
#define CP_WAIT1()  asm volatile("cp.async.wait_group 1;" ::: "memory")

__device__ __forceinline__ void mma_f16(float* c, const uint32_t* a, const uint32_t* b) {
    asm volatile(
        "mma.sync.aligned.m16n8k16.row.col.f32.f16.f16.f32 "
        "{%0,%1,%2,%3}, {%4,%5,%6,%7}, {%8,%9}, {%0,%1,%2,%3};"
        : "+f"(c[0]), "+f"(c[1]), "+f"(c[2]), "+f"(c[3])
        : "r"(a[0]), "r"(a[1]), "r"(a[2]), "r"(a[3]), "r"(b[0]), "r"(b[1]));
}

// ---------------------------------------------------------------------------
// Kernel 1: per-128 FWHT -> fp16, stored k-interleaved.
// ---------------------------------------------------------------------------
__global__ void __launch_bounds__(256) fwht_kernel(const float* __restrict__ in,
                                                   __half* __restrict__ out) {
    const int warp = (blockIdx.x << 3) | (threadIdx.x >> 5);
    const int lane = threadIdx.x & 31;
    const size_t base = (size_t)warp * 128;

    float4 v = reinterpret_cast<const float4*>(in + base)[lane];
    float a = v.x, b = v.y, c = v.z, d = v.w, t;
    t = a; a = a + b; b = t - b;
    t = c; c = c + d; d = t - d;
    t = a; a = a + c; c = t - c;
    t = b; b = b + d; d = t - d;
    #pragma unroll
    for (int mask = 1; mask <= 16; mask <<= 1) {
        float oa = __shfl_xor_sync(0xFFFFFFFFu, a, mask);
        float ob = __shfl_xor_sync(0xFFFFFFFFu, b, mask);
        float oc = __shfl_xor_sync(0xFFFFFFFFu, c, mask);
        float od = __shfl_xor_sync(0xFFFFFFFFu, d, mask);
        const bool hi = (lane & mask) != 0;
        a = hi ? (oa - a) : (a + oa);
        b = hi ? (ob - b) : (b + ob);
        c = hi ? (oc - c) : (c + oc);
        d = hi ? (od - d) : (d + od);
    }
    const float s = 0.08838834764831845f;
    __half2 h01 = __floats2half2_rn(a * s, b * s);
    __half2 h23 = __floats2half2_rn(c * s, d * s);

    const int q = lane >> 2;
    const int g = (lane >> 1) & 1;
    const int off = 16 * q + 2 * g + ((lane & 1) ? 8 : 0);
    __half2* o2 = reinterpret_cast<__half2*>(out + base);
    o2[off >> 1]       = h01;
    o2[(off >> 1) + 2] = h23;
}

// ---------------------------------------------------------------------------
// Kernel 2: trellis decode -> fp16, stored k-interleaved.
// ---------------------------------------------------------------------------
__global__ void __launch_bounds__(256) decode_kernel(const int* __restrict__ trellis,
                                                     const float* __restrict__ tlut,
                                                     const float* __restrict__ scales,
                                                     __half* __restrict__ W) {
    const int nb = blockIdx.x;
    const int t  = threadIdx.x;

    __shared__ uint32_t w[32];
    if (t < 32) w[t] = (uint32_t)trellis[nb * 32 + t] & 0xFFFFu;
    __syncthreads();

    const int p   = t << 1;
    const int i   = p >> 4;
    const int off = p & 15;
    const uint32_t s = (w[i] << 16) | w[(i + 1) & 31];
    const uint32_t state = (s >> (16 - off)) & 0xFFFFu;

    const float val = tlut[state];

    const int rb = nb >> 8;
    const int cb = nb & 255;
    const int tx = t >> 4;
    const int ty = t & 15;
    const int row = rb * 16 + tx;
    const int col = cb * 16 + ty;

    const float sc = scales[row * (IN_F / 128) + (col >> 7)];
    const int k = col & 15;
    const int pos = 4 * ((k & 7) >> 1) + ((k >> 3) << 1) + (k & 1);
    const int colstore = (col & ~15) | pos;
    W[(size_t)row * IN_F + colstore] = __float2half_rn(val * sc);
}

// ---------------------------------------------------------------------------
// Kernel 3: fp16 mma.sync GEMM with register fragment double-buffering.
// 128x256 CTA tile, BK=64, 3-stage cp.async pipeline, 8 warps x (64x64).
// ---------------------------------------------------------------------------
__global__ void __launch_bounds__(256, 1) gemm_mma_kernel(const __half* __restrict__ A,
                                                          const __half* __restrict__ B,
                                                          float* __restrict__ C) {
    extern __shared__ __half smem[];
    const uint32_t sbase = smem_to_u32(smem);

    const int tid  = threadIdx.x;
    const int lane = tid & 31;
    const int warp = tid >> 5;
    const int warp_m = warp >> 2;          // 0..1  -> 64-row slice
    const int warp_n = warp & 3;           // 0..3  -> 64-col slice

    // swizzle: supertiles of 8 m-blocks x 16 n-blocks
    const int bid = blockIdx.x;
    const int sm_ = bid >> 7;
    const int w_  = bid & 127;
    const int bm  = ((sm_ << 3) | (w_ & 7)) * BM;
    const int bn  = (w_ >> 3) * BN;

    const int lrow   = tid >> 3;           // 0..31
    const int lchunk = (tid & 7) << 3;     // half offset 0,8,...,56

    const __half* Ag = A + (size_t)(bm + lrow) * IN_F + lchunk;
    const __half* Bg = B + (size_t)(bn + lrow) * IN_F + lchunk;

    auto load_stage = [&](int buf, int kt) {
        const uint32_t sA = sbase + (uint32_t)(buf * STAGE_HALFS) * 2;
        const uint32_t sB = sA + (uint32_t)A_TILE_HALFS * 2;
        const int koff = kt * BK;
        #pragma unroll
        for (int r = 0; r < 4; r++)
            cp_async16(sA + (uint32_t)((lrow + (r << 5)) * P + lchunk) * 2,
                       Ag + (size_t)(r << 5) * IN_F + koff);
        #pragma unroll
        for (int r = 0; r < 8; r++)
            cp_async16(sB + (uint32_t)((lrow + (r << 5)) * P + lchunk) * 2,
                       Bg + (size_t)(r << 5) * IN_F + koff);
    };

    float acc[4][8][4];
    #pragma unroll
    for (int i = 0; i < 4; i++)
        #pragma unroll
        for (int j = 0; j < 8; j++)
            #pragma unroll
            for (int r = 0; r < 4; r++) acc[i][j][r] = 0.0f;

    #pragma unroll
    for (int s = 0; s < STAGES - 1; s++) {
        load_stage(s, s);
        CP_COMMIT();
    }

    const int lq = lane >> 2;              // 0..7
    const int lr = lane & 3;               // 0..3
    const uint32_t aw_off = (uint32_t)((warp_m * 64 + lq) * P + 4 * lr);
    const uint32_t bw_off = (uint32_t)((warp_n * 64 + lq) * P + 4 * lr);

    uint32_t af[2][4][4], bf[2][8][2];

    auto load_frags = [&](const __half* Aw, const __half* Bw, int ksp, int pb) {
        const int k0 = ksp << 4;
        #pragma unroll
        for (int mt = 0; mt < 4; mt++) {
            uint2 lo = *reinterpret_cast<const uint2*>(Aw + (mt * 16) * P + k0);
            uint2 hi = *reinterpret_cast<const uint2*>(Aw + (mt * 16 + 8) * P + k0);
            af[pb][mt][0] = lo.x;
            af[pb][mt][1] = hi.x;
            af[pb][mt][2] = lo.y;
            af[pb][mt][3] = hi.y;
        }
        #pragma unroll
        for (int nt = 0; nt < 8; nt++) {
            uint2 b = *reinterpret_cast<const uint2*>(Bw + (nt * 8) * P + k0);
            bf[pb][nt][0] = b.x;
            bf[pb][nt][1] = b.y;
        }
    };

    for (int kt = 0; kt < NKT; kt++) {
        CP_WAIT1();
        __syncthreads();

        const int buf = kt % STAGES;
        const __half* As = smem + buf * STAGE_HALFS;
        const __half* Bs = As + A_TILE_HALFS;
        const __half* Aw = As + aw_off;
        const __half* Bw = Bs + bw_off;

        // start fragment pipeline for this stage BEFORE issuing next cp.asyncs
        load_frags(Aw, Bw, 0, 0);

        if (kt + STAGES - 1 < NKT) load_stage((kt + STAGES - 1) % STAGES, kt + STAGES - 1);
        CP_COMMIT();

        #pragma unroll
        for (int ksp = 0; ksp < 4; ksp++) {
            const int cur = ksp & 1;
            if (ksp < 3) load_frags(Aw, Bw, ksp + 1, cur ^ 1);
            #pragma unroll
            for (int mt = 0; mt < 4; mt++)
                #pragma unroll
                for (int nt = 0; nt < 8; nt++)
                    mma_f16(acc[mt][nt], af[cur][mt], bf[cur][nt]);
        }
    }

    // epilogue
    const int crow = bm + warp_m * 64 + lq;
    const int ccol = bn + warp_n * 64 + 2 * lr;
    #pragma unroll
    for (int mt = 0; mt < 4; mt++) {
        #pragma unroll
        for (int nt = 0; nt < 8; nt++) {
            float* p0 = C + (size_t)(crow + mt * 16) * OUT_F + ccol + nt * 8;
            float* p1 = p0 + (size_t)8 * OUT_F;
            *reinterpret_cast<float2*>(p0) = make_float2(acc[mt][nt][0], acc[mt][nt][1]);
            *reinterpret_cast<float2*>(p1) = make_float2(acc[mt][nt][2], acc[mt][nt][3]);
        }
    }
}

// ---------------------------------------------------------------------------
extern "C" void kernel_launch(void* const* d_in, const int* in_sizes, int n_in,
                              void* d_out, int out_size) {
    const float* input   = (const float*)d_in[0];
    const int*   trellis = (const int*)  d_in[1];
    const float* tlut    = (const float*)d_in[2];
    const float* scales  = (const float*)d_in[3];
    float*       out     = (float*)d_out;

    __half* xbuf; __half* wbuf;
    cudaGetSymbolAddress((void**)&xbuf, g_x);
    cudaGetSymbolAddress((void**)&wbuf, g_W);

    fwht_kernel<<<(M_TOT * (IN_F / 128)) / 8, 256>>>(input, xbuf);
    decode_kernel<<<NB, 256>>>(trellis, tlut, scales, wbuf);

    static bool attr_set = false;
    if (!attr_set) {
        cudaFuncSetAttribute(gemm_mma_kernel,
                             cudaFuncAttributeMaxDynamicSharedMemorySize, SMEM_TOTAL);
        attr_set = true;
    }
    const int nblocks = (M_TOT / BM) * (OUT_F / BN);   // 1024
    gemm_mma_kernel<<<nblocks, 256, SMEM_TOTAL>>>(xbuf, wbuf, out);
}

// round 13
// speedup vs baseline: 2.1073x; 1.0852x over previous
#include <cuda_runtime.h>
#include <cuda_fp16.h>
#include <cstdint>

// ---------------- problem constants ----------------
constexpr int IN_F  = 4096;
constexpr int OUT_F = 4096;
constexpr int M_TOT = 8192;
constexpr int NB    = (OUT_F / 16) * (IN_F / 16);   // 65536 tiles

// ---------------- GEMM tiling ----------------
constexpr int BM = 128;
constexpr int BN = 256;
constexpr int BK = 64;                    // halfs of K per stage (128 B rows)
constexpr int STAGES = 4;
constexpr int NKT = IN_F / BK;            // 64 k-iterations
constexpr int ROW_B = 128;                // bytes per smem row (64 halfs, no pad)
constexpr int A_TILE_B = BM * ROW_B;      // 16384
constexpr int B_TILE_B = BN * ROW_B;      // 32768
constexpr int STAGE_B  = A_TILE_B + B_TILE_B;       // 49152
constexpr int SMEM_TOTAL = STAGES * STAGE_B;        // 196608

// ---------------- scratch (fp16, natural k-order) ----------------
__device__ __half g_x[(size_t)M_TOT * IN_F];
__device__ __half g_W[(size_t)OUT_F * IN_F];

// ---------------- helpers ----------------
__device__ __forceinline__ uint32_t smem_to_u32(const void* p) {
    uint32_t a;
    asm("{ .reg .u64 t; cvta.to.shared.u64 t, %1; cvt.u32.u64 %0, t; }" : "=r"(a) : "l"(p));
    return a;
}
__device__ __forceinline__ void cp_async16(uint32_t dst, const void* src) {
    asm volatile("cp.async.cg.shared.global [%0], [%1], 16;" :: "r"(dst), "l"(src) : "memory");
}
#define CP_COMMIT() asm volatile("cp.async.commit_group;" ::: "memory")
#define CP_WAIT2()  asm volatile("cp.async.wait_group 2;" ::: "memory")

__device__ __forceinline__ void ldsm_x4(uint32_t* r, uint32_t addr) {
    asm volatile("ldmatrix.sync.aligned.m8n8.x4.shared.b16 {%0,%1,%2,%3}, [%4];"
                 : "=r"(r[0]), "=r"(r[1]), "=r"(r[2]), "=r"(r[3]) : "r"(addr));
}
__device__ __forceinline__ void mma_f16(float* c, const uint32_t* a, const uint32_t* b) {
    asm volatile(
        "mma.sync.aligned.m16n8k16.row.col.f32.f16.f16.f32 "
        "{%0,%1,%2,%3}, {%4,%5,%6,%7}, {%8,%9}, {%0,%1,%2,%3};"
        : "+f"(c[0]), "+f"(c[1]), "+f"(c[2]), "+f"(c[3])
        : "r"(a[0]), "r"(a[1]), "r"(a[2]), "r"(a[3]), "r"(b[0]), "r"(b[1]));
}

// ---------------------------------------------------------------------------
// Kernel 1: per-128 FWHT -> fp16, natural order.
// ---------------------------------------------------------------------------
__global__ void __launch_bounds__(256) fwht_kernel(const float* __restrict__ in,
                                                   __half* __restrict__ out) {
    const int warp = (blockIdx.x << 3) | (threadIdx.x >> 5);
    const int lane = threadIdx.x & 31;
    const size_t base = (size_t)warp * 128;

    float4 v = reinterpret_cast<const float4*>(in + base)[lane];
    float a = v.x, b = v.y, c = v.z, d = v.w, t;
    t = a; a = a + b; b = t - b;
    t = c; c = c + d; d = t - d;
    t = a; a = a + c; c = t - c;
    t = b; b = b + d; d = t - d;
    #pragma unroll
    for (int mask = 1; mask <= 16; mask <<= 1) {
        float oa = __shfl_xor_sync(0xFFFFFFFFu, a, mask);
        float ob = __shfl_xor_sync(0xFFFFFFFFu, b, mask);
        float oc = __shfl_xor_sync(0xFFFFFFFFu, c, mask);
        float od = __shfl_xor_sync(0xFFFFFFFFu, d, mask);
        const bool hi = (lane & mask) != 0;
        a = hi ? (oa - a) : (a + oa);
        b = hi ? (ob - b) : (b + ob);
        c = hi ? (oc - c) : (c + oc);
        d = hi ? (od - d) : (d + od);
    }
    const float s = 0.08838834764831845f;
    __half2 h01 = __floats2half2_rn(a * s, b * s);
    __half2 h23 = __floats2half2_rn(c * s, d * s);
    __half2* o2 = reinterpret_cast<__half2*>(out + base);
    o2[2 * lane]     = h01;
    o2[2 * lane + 1] = h23;
}

// ---------------------------------------------------------------------------
// Kernel 2: trellis decode -> fp16, natural order.
// ---------------------------------------------------------------------------
__global__ void __launch_bounds__(256) decode_kernel(const int* __restrict__ trellis,
                                                     const float* __restrict__ tlut,
                                                     const float* __restrict__ scales,
                                                     __half* __restrict__ W) {
    const int nb = blockIdx.x;
    const int t  = threadIdx.x;

    __shared__ uint32_t w[32];
    if (t < 32) w[t] = (uint32_t)trellis[nb * 32 + t] & 0xFFFFu;
    __syncthreads();

    const int p   = t << 1;
    const int i   = p >> 4;
    const int off = p & 15;
    const uint32_t s = (w[i] << 16) | w[(i + 1) & 31];
    const uint32_t state = (s >> (16 - off)) & 0xFFFFu;

    const float val = tlut[state];

    const int rb = nb >> 8;
    const int cb = nb & 255;
    const int tx = t >> 4;
    const int ty = t & 15;
    const int row = rb * 16 + tx;
    const int col = cb * 16 + ty;

    const float sc = scales[row * (IN_F / 128) + (col >> 7)];
    W[(size_t)row * IN_F + col] = __float2half_rn(val * sc);
}

// ---------------------------------------------------------------------------
// Kernel 3: fp16 mma.sync GEMM, ldmatrix fragments, XOR-swizzled smem,
// 128x256 CTA tile, BK=64, 4-stage cp.async pipeline, 8 warps x (64x64).
// ---------------------------------------------------------------------------
__global__ void __launch_bounds__(256, 1) gemm_mma_kernel(const __half* __restrict__ A,
                                                          const __half* __restrict__ B,
                                                          float* __restrict__ C) {
    extern __shared__ __half smem[];
    const uint32_t sbase = smem_to_u32(smem);

    const int tid  = threadIdx.x;
    const int lane = tid & 31;
    const int warp = tid >> 5;
    const int warp_m = warp >> 2;          // 0..1  -> 64-row slice
    const int warp_n = warp & 3;           // 0..3  -> 64-col slice

    // swizzle: supertiles of 8 m-blocks x 16 n-blocks
    const int bid = blockIdx.x;
    const int sm_ = bid >> 7;
    const int w_  = bid & 127;
    const int bm  = ((sm_ << 3) | (w_ & 7)) * BM;
    const int bn  = (w_ >> 3) * BN;

    // ---- global -> smem (cp.async, XOR swizzle on 16B chunks) ----
    const int lrow   = tid >> 3;                 // 0..31
    const int lchunk = tid & 7;                  // 16B chunk in row
    const uint32_t wchunk = (uint32_t)((lchunk ^ (lrow & 7)) << 4);   // swizzled byte off

    const __half* Ag = A + (size_t)(bm + lrow) * IN_F + (lchunk << 3);
    const __half* Bg = B + (size_t)(bn + lrow) * IN_F + (lchunk << 3);

    auto load_stage = [&](int buf, int kt) {
        const uint32_t sA = sbase + (uint32_t)buf * STAGE_B;
        const uint32_t sB = sA + A_TILE_B;
        const int koff = kt * BK;
        #pragma unroll
        for (int r = 0; r < 4; r++)
            cp_async16(sA + (uint32_t)(lrow + (r << 5)) * ROW_B + wchunk,
                       Ag + (size_t)(r << 5) * IN_F + koff);
        #pragma unroll
        for (int r = 0; r < 8; r++)
            cp_async16(sB + (uint32_t)(lrow + (r << 5)) * ROW_B + wchunk,
                       Bg + (size_t)(r << 5) * IN_F + koff);
    };

    // ---- ldmatrix addresses (per-lane constants except ksp/stage) ----
    // A: matrices (m lo/hi = (lane>>3)&1, k lo/hi = lane>>4), row bits = lane&7
    const int a_row = warp_m * 64 + (((lane >> 3) & 1) << 3) + (lane & 7);
    const int a_kbit = lane >> 4;                       // 0/1
    // B: matrices (k lo/hi = (lane>>3)&1, n lo/hi = (lane>>4)&1)
    const int b_row = warp_n * 64 + (((lane >> 4) & 1) << 3) + (lane & 7);
    const int b_kbit = (lane >> 3) & 1;
    const int sw = lane & 7;                            // swizzle XOR value

    const uint32_t a_base = (uint32_t)a_row * ROW_B;    // + mt*16*ROW_B
    const uint32_t b_base = (uint32_t)b_row * ROW_B;    // + nn*16*ROW_B

    float acc[4][8][4];
    #pragma unroll
    for (int i = 0; i < 4; i++)
        #pragma unroll
        for (int j = 0; j < 8; j++)
            #pragma unroll
            for (int r = 0; r < 4; r++) acc[i][j][r] = 0.0f;

    #pragma unroll
    for (int s = 0; s < STAGES - 1; s++) {
        load_stage(s, s);
        CP_COMMIT();
    }

    uint32_t af[2][4][4], bf[2][4][4];   // bf[.][nn][r]: r0,r1 = tile 2nn; r2,r3 = tile 2nn+1

    auto load_frags = [&](uint32_t sA, uint32_t sB, int ksp, int pb) {
        const uint32_t akx = (uint32_t)(((2 * ksp + a_kbit) ^ sw) << 4);
        const uint32_t bkx = (uint32_t)(((2 * ksp + b_kbit) ^ sw) << 4);
        #pragma unroll
        for (int mt = 0; mt < 4; mt++)
            ldsm_x4(af[pb][mt], sA + a_base + (uint32_t)(mt * 16) * ROW_B + akx);
        #pragma unroll
        for (int nn = 0; nn < 4; nn++)
            ldsm_x4(bf[pb][nn], sB + b_base + (uint32_t)(nn * 16) * ROW_B + bkx);
    };

    const int lq = lane >> 2;
    const int lr = lane & 3;

    for (int kt = 0; kt < NKT; kt++) {
        CP_WAIT2();
        __syncthreads();

        const uint32_t sA = sbase + (uint32_t)(kt % STAGES) * STAGE_B;
        const uint32_t sB = sA + A_TILE_B;

        load_frags(sA, sB, 0, 0);

        if (kt + STAGES - 1 < NKT) load_stage((kt + STAGES - 1) % STAGES, kt + STAGES - 1);
        CP_COMMIT();

        #pragma unroll
        for (int ksp = 0; ksp < 4; ksp++) {
            const int cur = ksp & 1;
            if (ksp < 3) load_frags(sA, sB, ksp + 1, cur ^ 1);
            #pragma unroll
            for (int mt = 0; mt < 4; mt++)
                #pragma unroll
                for (int nn = 0; nn < 4; nn++) {
                    mma_f16(acc[mt][2 * nn],     af[cur][mt], &bf[cur][nn][0]);
                    mma_f16(acc[mt][2 * nn + 1], af[cur][mt], &bf[cur][nn][2]);
                }
        }
    }

    // epilogue
    const int crow = bm + warp_m * 64 + lq;
    const int ccol = bn + warp_n * 64 + 2 * lr;
    #pragma unroll
    for (int mt = 0; mt < 4; mt++) {
        #pragma unroll
        for (int nt = 0; nt < 8; nt++) {
            float* p0 = C + (size_t)(crow + mt * 16) * OUT_F + ccol + nt * 8;
            float* p1 = p0 + (size_t)8 * OUT_F;
            *reinterpret_cast<float2*>(p0) = make_float2(acc[mt][nt][0], acc[mt][nt][1]);
            *reinterpret_cast<float2*>(p1) = make_float2(acc[mt][nt][2], acc[mt][nt][3]);
        }
    }
}

// ---------------------------------------------------------------------------
extern "C" void kernel_launch(void* const* d_in, const int* in_sizes, int n_in,
                              void* d_out, int out_size) {
    const float* input   = (const float*)d_in[0];
    const int*   trellis = (const int*)  d_in[1];
    const float* tlut    = (const float*)d_in[2];
    const float* scales  = (const float*)d_in[3];
    float*       out     = (float*)d_out;

    __half* xbuf; __half* wbuf;
    cudaGetSymbolAddress((void**)&xbuf, g_x);
    cudaGetSymbolAddress((void**)&wbuf, g_W);

    fwht_kernel<<<(M_TOT * (IN_F / 128)) / 8, 256>>>(input, xbuf);
    decode_kernel<<<NB, 256>>>(trellis, tlut, scales, wbuf);

    static bool attr_set = false;
    if (!attr_set) {
        cudaFuncSetAttribute(gemm_mma_kernel,
                             cudaFuncAttributeMaxDynamicSharedMemorySize, SMEM_TOTAL);
        attr_set = true;
    }
    const int nblocks = (M_TOT / BM) * (OUT_F / BN);   // 1024
    gemm_mma_kernel<<<nblocks, 256, SMEM_TOTAL>>>(xbuf, wbuf, out);
}

// round 14
// speedup vs baseline: 2.2413x; 1.0635x over previous
#include <cuda_runtime.h>
#include <cuda_fp16.h>
#include <cstdint>

// ---------------- problem constants ----------------
constexpr int IN_F  = 4096;
constexpr int OUT_F = 4096;
constexpr int M_TOT = 8192;
constexpr int NB    = (OUT_F / 16) * (IN_F / 16);   // 65536 tiles

// ---------------- GEMM tiling ----------------
constexpr int BM = 128;
constexpr int BN = 256;
constexpr int BK = 64;                    // halfs of K per stage (128 B rows)
constexpr int STAGES = 4;
constexpr int NKT = IN_F / BK;            // 64 k-iterations
constexpr int ROW_B = 128;                // bytes per smem row (64 halfs, no pad)
constexpr int A_TILE_B = BM * ROW_B;      // 16384
constexpr int B_TILE_B = BN * ROW_B;      // 32768
constexpr int STAGE_B  = A_TILE_B + B_TILE_B;       // 49152
constexpr int SMEM_TOTAL = STAGES * STAGE_B;        // 196608

// ---------------- scratch (fp16, natural k-order) ----------------
__device__ __half g_x[(size_t)M_TOT * IN_F];
__device__ __half g_W[(size_t)OUT_F * IN_F];

// ---------------- helpers ----------------
__device__ __forceinline__ uint32_t smem_to_u32(const void* p) {
    uint32_t a;
    asm("{ .reg .u64 t; cvta.to.shared.u64 t, %1; cvt.u32.u64 %0, t; }" : "=r"(a) : "l"(p));
    return a;
}
__device__ __forceinline__ void cp_async16(uint32_t dst, const void* src) {
    asm volatile("cp.async.cg.shared.global [%0], [%1], 16;" :: "r"(dst), "l"(src) : "memory");
}
#define CP_COMMIT() asm volatile("cp.async.commit_group;" ::: "memory")
#define CP_WAIT2()  asm volatile("cp.async.wait_group 2;" ::: "memory")

__device__ __forceinline__ void ldsm_x4(uint32_t* r, uint32_t addr) {
    asm volatile("ldmatrix.sync.aligned.m8n8.x4.shared.b16 {%0,%1,%2,%3}, [%4];"
                 : "=r"(r[0]), "=r"(r[1]), "=r"(r[2]), "=r"(r[3]) : "r"(addr));
}
__device__ __forceinline__ void mma_f16(float* c, const uint32_t* a, const uint32_t* b) {
    asm volatile(
        "mma.sync.aligned.m16n8k16.row.col.f32.f16.f16.f32 "
        "{%0,%1,%2,%3}, {%4,%5,%6,%7}, {%8,%9}, {%0,%1,%2,%3};"
        : "+f"(c[0]), "+f"(c[1]), "+f"(c[2]), "+f"(c[3])
        : "r"(a[0]), "r"(a[1]), "r"(a[2]), "r"(a[3]), "r"(b[0]), "r"(b[1]));
}

// ---------------------------------------------------------------------------
// Kernel 1 (fused): blocks [0, 32768) do FWHT; blocks [32768, 98304) decode.
// Independent outputs -> safe to run concurrently; overlaps HBM-bound FWHT
// with L2/LUT-bound decode.
// ---------------------------------------------------------------------------
constexpr int FWHT_BLOCKS = (M_TOT * (IN_F / 128)) / 8;   // 32768

__global__ void __launch_bounds__(256) prep_kernel(const float* __restrict__ in,
                                                   __half* __restrict__ xout,
                                                   const int* __restrict__ trellis,
                                                   const float* __restrict__ tlut,
                                                   const float* __restrict__ scales,
                                                   __half* __restrict__ W) {
    if (blockIdx.x < FWHT_BLOCKS) {
        // ---- FWHT part ----
        const int warp = (blockIdx.x << 3) | (threadIdx.x >> 5);
        const int lane = threadIdx.x & 31;
        const size_t base = (size_t)warp * 128;

        float4 v = reinterpret_cast<const float4*>(in + base)[lane];
        float a = v.x, b = v.y, c = v.z, d = v.w, t;
        t = a; a = a + b; b = t - b;
        t = c; c = c + d; d = t - d;
        t = a; a = a + c; c = t - c;
        t = b; b = b + d; d = t - d;
        #pragma unroll
        for (int mask = 1; mask <= 16; mask <<= 1) {
            float oa = __shfl_xor_sync(0xFFFFFFFFu, a, mask);
            float ob = __shfl_xor_sync(0xFFFFFFFFu, b, mask);
            float oc = __shfl_xor_sync(0xFFFFFFFFu, c, mask);
            float od = __shfl_xor_sync(0xFFFFFFFFu, d, mask);
            const bool hi = (lane & mask) != 0;
            a = hi ? (oa - a) : (a + oa);
            b = hi ? (ob - b) : (b + ob);
            c = hi ? (oc - c) : (c + oc);
            d = hi ? (od - d) : (d + od);
        }
        const float s = 0.08838834764831845f;
        __half2 h01 = __floats2half2_rn(a * s, b * s);
        __half2 h23 = __floats2half2_rn(c * s, d * s);
        uint2 pk = make_uint2(*reinterpret_cast<uint32_t*>(&h01),
                              *reinterpret_cast<uint32_t*>(&h23));
        reinterpret_cast<uint2*>(xout + base)[lane] = pk;
    } else {
        // ---- decode part ----
        const int nb = blockIdx.x - FWHT_BLOCKS;
        const int t  = threadIdx.x;

        __shared__ uint32_t w[32];
        if (t < 32) w[t] = (uint32_t)trellis[nb * 32 + t] & 0xFFFFu;
        __syncthreads();

        const int p   = t << 1;
        const int i   = p >> 4;
        const int off = p & 15;
        const uint32_t s = (w[i] << 16) | w[(i + 1) & 31];
        const uint32_t state = (s >> (16 - off)) & 0xFFFFu;

        const float val = tlut[state];

        const int rb = nb >> 8;
        const int cb = nb & 255;
        const int tx = t >> 4;
        const int ty = t & 15;
        const int row = rb * 16 + tx;
        const int col = cb * 16 + ty;

        const float sc = scales[row * (IN_F / 128) + (col >> 7)];
        W[(size_t)row * IN_F + col] = __float2half_rn(val * sc);
    }
}

// ---------------------------------------------------------------------------
// Kernel 2: fp16 mma.sync GEMM, ldmatrix fragments, XOR-swizzled smem,
// 128x256 CTA tile, BK=64, 4-stage cp.async pipeline, 8 warps x (64x64).
// cp.asyncs spread across the ksp loop to smooth issue pressure.
// ---------------------------------------------------------------------------
__global__ void __launch_bounds__(256, 1) gemm_mma_kernel(const __half* __restrict__ A,
                                                          const __half* __restrict__ B,
                                                          float* __restrict__ C) {
    extern __shared__ __half smem[];
    const uint32_t sbase = smem_to_u32(smem);

    const int tid  = threadIdx.x;
    const int lane = tid & 31;
    const int warp = tid >> 5;
    const int warp_m = warp >> 2;          // 0..1  -> 64-row slice
    const int warp_n = warp & 3;           // 0..3  -> 64-col slice

    // supertiles of 8 m-blocks x 16 n-blocks
    const int bid = blockIdx.x;
    const int sm_ = bid >> 7;
    const int w_  = bid & 127;
    const int bm  = ((sm_ << 3) | (w_ & 7)) * BM;
    const int bn  = (w_ >> 3) * BN;

    // ---- global -> smem (cp.async, XOR swizzle on 16B chunks) ----
    const int lrow   = tid >> 3;                 // 0..31
    const int lchunk = tid & 7;                  // 16B chunk in row
    const uint32_t wchunk = (uint32_t)((lchunk ^ (lrow & 7)) << 4);

    const __half* Ag = A + (size_t)(bm + lrow) * IN_F + (lchunk << 3);
    const __half* Bg = B + (size_t)(bn + lrow) * IN_F + (lchunk << 3);

    // part 0: A rows; part 1: B rows 0..127; part 2: B rows 128..255
    auto load_part = [&](int buf, int kt, int part) {
        const uint32_t sA = sbase + (uint32_t)buf * STAGE_B;
        const int koff = kt * BK;
        if (part == 0) {
            #pragma unroll
            for (int r = 0; r < 4; r++)
                cp_async16(sA + (uint32_t)(lrow + (r << 5)) * ROW_B + wchunk,
                           Ag + (size_t)(r << 5) * IN_F + koff);
        } else if (part == 1) {
            const uint32_t sB = sA + A_TILE_B;
            #pragma unroll
            for (int r = 0; r < 4; r++)
                cp_async16(sB + (uint32_t)(lrow + (r << 5)) * ROW_B + wchunk,
                           Bg + (size_t)(r << 5) * IN_F + koff);
        } else {
            const uint32_t sB = sA + A_TILE_B;
            #pragma unroll
            for (int r = 4; r < 8; r++)
                cp_async16(sB + (uint32_t)(lrow + (r << 5)) * ROW_B + wchunk,
                           Bg + (size_t)(r << 5) * IN_F + koff);
        }
    };

    // ---- ldmatrix addresses ----
    const int a_row  = warp_m * 64 + (((lane >> 3) & 1) << 3) + (lane & 7);
    const int a_kbit = lane >> 4;
    const int b_row  = warp_n * 64 + (((lane >> 4) & 1) << 3) + (lane & 7);
    const int b_kbit = (lane >> 3) & 1;
    const int sw     = lane & 7;

    const uint32_t a_base = (uint32_t)a_row * ROW_B;
    const uint32_t b_base = (uint32_t)b_row * ROW_B;

    float acc[4][8][4];
    #pragma unroll
    for (int i = 0; i < 4; i++)
        #pragma unroll
        for (int j = 0; j < 8; j++)
            #pragma unroll
            for (int r = 0; r < 4; r++) acc[i][j][r] = 0.0f;

    #pragma unroll
    for (int s = 0; s < STAGES - 1; s++) {
        load_part(s, s, 0);
        load_part(s, s, 1);
        load_part(s, s, 2);
        CP_COMMIT();
    }

    uint32_t af[2][4][4], bf[2][4][4];

    auto load_frags = [&](uint32_t sA, uint32_t sB, int ksp, int pb) {
        const uint32_t akx = (uint32_t)(((2 * ksp + a_kbit) ^ sw) << 4);
        const uint32_t bkx = (uint32_t)(((2 * ksp + b_kbit) ^ sw) << 4);
        #pragma unroll
        for (int mt = 0; mt < 4; mt++)
            ldsm_x4(af[pb][mt], sA + a_base + (uint32_t)(mt * 16) * ROW_B + akx);
        #pragma unroll
        for (int nn = 0; nn < 4; nn++)
            ldsm_x4(bf[pb][nn], sB + b_base + (uint32_t)(nn * 16) * ROW_B + bkx);
    };

    const int lq = lane >> 2;
    const int lr = lane & 3;

    for (int kt = 0; kt < NKT; kt++) {
        CP_WAIT2();
        __syncthreads();

        const uint32_t sA = sbase + (uint32_t)(kt % STAGES) * STAGE_B;
        const uint32_t sB = sA + A_TILE_B;

        load_frags(sA, sB, 0, 0);

        const bool pf   = (kt + STAGES - 1 < NKT);
        const int  pbuf = (kt + STAGES - 1) % STAGES;
        const int  pkt  = kt + STAGES - 1;

        #pragma unroll
        for (int ksp = 0; ksp < 4; ksp++) {
            const int cur = ksp & 1;
            if (ksp < 3) {
                load_frags(sA, sB, ksp + 1, cur ^ 1);
                if (pf) load_part(pbuf, pkt, ksp);   // spread cp.asyncs
            }
            #pragma unroll
            for (int mt = 0; mt < 4; mt++)
                #pragma unroll
                for (int nn = 0; nn < 4; nn++) {
                    mma_f16(acc[mt][2 * nn],     af[cur][mt], &bf[cur][nn][0]);
                    mma_f16(acc[mt][2 * nn + 1], af[cur][mt], &bf[cur][nn][2]);
                }
        }
        CP_COMMIT();   // unconditional: keeps group<->stage accounting exact
    }

    // epilogue
    const int crow = bm + warp_m * 64 + lq;
    const int ccol = bn + warp_n * 64 + 2 * lr;
    #pragma unroll
    for (int mt = 0; mt < 4; mt++) {
        #pragma unroll
        for (int nt = 0; nt < 8; nt++) {
            float* p0 = C + (size_t)(crow + mt * 16) * OUT_F + ccol + nt * 8;
            float* p1 = p0 + (size_t)8 * OUT_F;
            *reinterpret_cast<float2*>(p0) = make_float2(acc[mt][nt][0], acc[mt][nt][1]);
            *reinterpret_cast<float2*>(p1) = make_float2(acc[mt][nt][2], acc[mt][nt][3]);
        }
    }
}

// ---------------------------------------------------------------------------
extern "C" void kernel_launch(void* const* d_in, const int* in_sizes, int n_in,
                              void* d_out, int out_size) {
    const float* input   = (const float*)d_in[0];
    const int*   trellis = (const int*)  d_in[1];
    const float* tlut    = (const float*)d_in[2];
    const float* scales  = (const float*)d_in[3];
    float*       out     = (float*)d_out;

    __half* xbuf; __half* wbuf;
    cudaGetSymbolAddress((void**)&xbuf, g_x);
    cudaGetSymbolAddress((void**)&wbuf, g_W);

    // 1) fused FWHT + decode (independent outputs, concurrent)
    prep_kernel<<<FWHT_BLOCKS + NB, 256>>>(input, xbuf, trellis, tlut, scales, wbuf);

    // 2) fp16 mma.sync GEMM
    static bool attr_set = false;
    if (!attr_set) {
        cudaFuncSetAttribute(gemm_mma_kernel,
                             cudaFuncAttributeMaxDynamicSharedMemorySize, SMEM_TOTAL);
        attr_set = true;
    }
    const int nblocks = (M_TOT / BM) * (OUT_F / BN);   // 1024
    gemm_mma_kernel<<<nblocks, 256, SMEM_TOTAL>>>(xbuf, wbuf, out);
}

// round 15
// speedup vs baseline: 2.4725x; 1.1032x over previous
#include <cuda_runtime.h>
#include <cuda_fp16.h>
#include <cstdint>

// ---------------- problem constants ----------------
constexpr int IN_F  = 4096;
constexpr int OUT_F = 4096;
constexpr int M_TOT = 8192;
constexpr int NB    = (OUT_F / 16) * (IN_F / 16);   // 65536 tiles

// ---------------- GEMM tiling ----------------
constexpr int BM = 128;
constexpr int BN = 256;
constexpr int BK = 64;                    // halfs of K per stage (128 B rows)
constexpr int STAGES = 4;
constexpr int NKT = IN_F / BK;            // 64 k-iterations
constexpr int ROW_B = 128;                // bytes per smem row
constexpr int A_TILE_B = BM * ROW_B;      // 16384
constexpr int B_TILE_B = BN * ROW_B;      // 32768
constexpr int STAGE_B  = A_TILE_B + B_TILE_B;       // 49152
constexpr int SMEM_TOTAL = STAGES * STAGE_B;        // 196608

// ---------------- scratch (fp16, natural k-order) ----------------
__device__ __half g_x[(size_t)M_TOT * IN_F];
__device__ __half g_W[(size_t)OUT_F * IN_F];

// ---------------- helpers ----------------
__device__ __forceinline__ uint32_t smem_to_u32(const void* p) {
    uint32_t a;
    asm("{ .reg .u64 t; cvta.to.shared.u64 t, %1; cvt.u32.u64 %0, t; }" : "=r"(a) : "l"(p));
    return a;
}
__device__ __forceinline__ void cp_async16(uint32_t dst, const void* src) {
    asm volatile("cp.async.cg.shared.global [%0], [%1], 16;" :: "r"(dst), "l"(src) : "memory");
}
#define CP_COMMIT() asm volatile("cp.async.commit_group;" ::: "memory")
#define CP_WAIT2()  asm volatile("cp.async.wait_group 2;" ::: "memory")

__device__ __forceinline__ void ldsm_x4(uint32_t* r, uint32_t addr) {
    asm volatile("ldmatrix.sync.aligned.m8n8.x4.shared.b16 {%0,%1,%2,%3}, [%4];"
                 : "=r"(r[0]), "=r"(r[1]), "=r"(r[2]), "=r"(r[3]) : "r"(addr));
}
__device__ __forceinline__ void mma_f16(float* c, const uint32_t* a, const uint32_t* b) {
    asm volatile(
        "mma.sync.aligned.m16n8k16.row.col.f32.f16.f16.f32 "
        "{%0,%1,%2,%3}, {%4,%5,%6,%7}, {%8,%9}, {%0,%1,%2,%3};"
        : "+f"(c[0]), "+f"(c[1]), "+f"(c[2]), "+f"(c[3])
        : "r"(a[0]), "r"(a[1]), "r"(a[2]), "r"(a[3]), "r"(b[0]), "r"(b[1]));
}

// ---------------------------------------------------------------------------
// Kernel 1 (fused, interleaved): blockIdx%3==0 -> FWHT (1/3), else decode (2/3).
// Ratio is exactly 32768 : 65536, so both kinds co-reside on the SMs.
// ---------------------------------------------------------------------------
constexpr int FWHT_BLOCKS = (M_TOT * (IN_F / 128)) / 8;   // 32768
constexpr int PREP_BLOCKS = FWHT_BLOCKS + NB;             // 98304

__global__ void __launch_bounds__(256) prep_kernel(const float* __restrict__ in,
                                                   __half* __restrict__ xout,
                                                   const int* __restrict__ trellis,
                                                   const float* __restrict__ tlut,
                                                   const float* __restrict__ scales,
                                                   __half* __restrict__ W) {
    const int bid = blockIdx.x;
    if (bid % 3 == 0) {
        // ---- FWHT part ----
        const int warp = ((bid / 3) << 3) | (threadIdx.x >> 5);
        const int lane = threadIdx.x & 31;
        const size_t base = (size_t)warp * 128;

        float4 v = reinterpret_cast<const float4*>(in + base)[lane];
        float a = v.x, b = v.y, c = v.z, d = v.w, t;
        t = a; a = a + b; b = t - b;
        t = c; c = c + d; d = t - d;
        t = a; a = a + c; c = t - c;
        t = b; b = b + d; d = t - d;
        #pragma unroll
        for (int mask = 1; mask <= 16; mask <<= 1) {
            float oa = __shfl_xor_sync(0xFFFFFFFFu, a, mask);
            float ob = __shfl_xor_sync(0xFFFFFFFFu, b, mask);
            float oc = __shfl_xor_sync(0xFFFFFFFFu, c, mask);
            float od = __shfl_xor_sync(0xFFFFFFFFu, d, mask);
            const bool hi = (lane & mask) != 0;
            a = hi ? (oa - a) : (a + oa);
            b = hi ? (ob - b) : (b + ob);
            c = hi ? (oc - c) : (c + oc);
            d = hi ? (od - d) : (d + od);
        }
        const float s = 0.08838834764831845f;
        __half2 h01 = __floats2half2_rn(a * s, b * s);
        __half2 h23 = __floats2half2_rn(c * s, d * s);
        uint2 pk = make_uint2(*reinterpret_cast<uint32_t*>(&h01),
                              *reinterpret_cast<uint32_t*>(&h23));
        reinterpret_cast<uint2*>(xout + base)[lane] = pk;
    } else {
        // ---- decode part ----
        const int nb = 2 * (bid / 3) + (bid % 3) - 1;
        const int t  = threadIdx.x;

        __shared__ uint32_t w[32];
        if (t < 32) w[t] = (uint32_t)trellis[nb * 32 + t] & 0xFFFFu;
        __syncthreads();

        const int p   = t << 1;
        const int i   = p >> 4;
        const int off = p & 15;
        const uint32_t s = (w[i] << 16) | w[(i + 1) & 31];
        const uint32_t state = (s >> (16 - off)) & 0xFFFFu;

        const float val = tlut[state];

        const int rb = nb >> 8;
        const int cb = nb & 255;
        const int tx = t >> 4;
        const int ty = t & 15;
        const int row = rb * 16 + tx;
        const int col = cb * 16 + ty;

        const float sc = scales[row * (IN_F / 128) + (col >> 7)];
        W[(size_t)row * IN_F + col] = __float2half_rn(val * sc);
    }
}

// ---------------------------------------------------------------------------
// Kernel 2: fp16 mma.sync GEMM, fragments software-pipelined ACROSS the kt
// boundary: barrier sits between ksp2 and ksp3 MMA batches; next stage's
// ksp0 fragments prefetched right after the barrier under ksp3's MMAs.
// ---------------------------------------------------------------------------
__global__ void __launch_bounds__(256, 1) gemm_mma_kernel(const __half* __restrict__ A,
                                                          const __half* __restrict__ B,
                                                          float* __restrict__ C) {
    extern __shared__ __half smem[];
    const uint32_t sbase = smem_to_u32(smem);

    const int tid  = threadIdx.x;
    const int lane = tid & 31;
    const int warp = tid >> 5;
    const int warp_m = warp >> 2;
    const int warp_n = warp & 3;

    // supertiles of 8 m-blocks x 16 n-blocks
    const int bid = blockIdx.x;
    const int sm_ = bid >> 7;
    const int w_  = bid & 127;
    const int bm  = ((sm_ << 3) | (w_ & 7)) * BM;
    const int bn  = (w_ >> 3) * BN;

    // ---- global -> smem (cp.async, XOR swizzle on 16B chunks) ----
    const int lrow   = tid >> 3;
    const int lchunk = tid & 7;
    const uint32_t wchunk = (uint32_t)((lchunk ^ (lrow & 7)) << 4);

    const __half* Ag = A + (size_t)(bm + lrow) * IN_F + (lchunk << 3);
    const __half* Bg = B + (size_t)(bn + lrow) * IN_F + (lchunk << 3);

    auto load_part = [&](int buf, int kt, int part) {
        const uint32_t sA = sbase + (uint32_t)buf * STAGE_B;
        const int koff = kt * BK;
        if (part == 0) {
            #pragma unroll
            for (int r = 0; r < 4; r++)
                cp_async16(sA + (uint32_t)(lrow + (r << 5)) * ROW_B + wchunk,
                           Ag + (size_t)(r << 5) * IN_F + koff);
        } else if (part == 1) {
            const uint32_t sB = sA + A_TILE_B;
            #pragma unroll
            for (int r = 0; r < 4; r++)
                cp_async16(sB + (uint32_t)(lrow + (r << 5)) * ROW_B + wchunk,
                           Bg + (size_t)(r << 5) * IN_F + koff);
        } else {
            const uint32_t sB = sA + A_TILE_B;
            #pragma unroll
            for (int r = 4; r < 8; r++)
                cp_async16(sB + (uint32_t)(lrow + (r << 5)) * ROW_B + wchunk,
                           Bg + (size_t)(r << 5) * IN_F + koff);
        }
    };

    // ---- ldmatrix addressing ----
    const int a_row  = warp_m * 64 + (((lane >> 3) & 1) << 3) + (lane & 7);
    const int a_kbit = lane >> 4;
    const int b_row  = warp_n * 64 + (((lane >> 4) & 1) << 3) + (lane & 7);
    const int b_kbit = (lane >> 3) & 1;
    const int sw     = lane & 7;

    const uint32_t a_base = (uint32_t)a_row * ROW_B;
    const uint32_t b_base = (uint32_t)b_row * ROW_B;

    float acc[4][8][4];
    #pragma unroll
    for (int i = 0; i < 4; i++)
        #pragma unroll
        for (int j = 0; j < 8; j++)
            #pragma unroll
            for (int r = 0; r < 4; r++) acc[i][j][r] = 0.0f;

    uint32_t af[2][4][4], bf[2][4][4];

    auto load_frags = [&](uint32_t stage_base, int ksp, int pb) {
        const uint32_t sA = stage_base;
        const uint32_t sB = stage_base + A_TILE_B;
        const uint32_t akx = (uint32_t)(((2 * ksp + a_kbit) ^ sw) << 4);
        const uint32_t bkx = (uint32_t)(((2 * ksp + b_kbit) ^ sw) << 4);
        #pragma unroll
        for (int mt = 0; mt < 4; mt++)
            ldsm_x4(af[pb][mt], sA + a_base + (uint32_t)(mt * 16) * ROW_B + akx);
        #pragma unroll
        for (int nn = 0; nn < 4; nn++)
            ldsm_x4(bf[pb][nn], sB + b_base + (uint32_t)(nn * 16) * ROW_B + bkx);
    };

    auto mma_batch = [&](int pb) {
        #pragma unroll
        for (int mt = 0; mt < 4; mt++)
            #pragma unroll
            for (int nn = 0; nn < 4; nn++) {
                mma_f16(acc[mt][2 * nn],     af[pb][mt], &bf[pb][nn][0]);
                mma_f16(acc[mt][2 * nn + 1], af[pb][mt], &bf[pb][nn][2]);
            }
    };

    // prologue: stages 0..2 in flight
    #pragma unroll
    for (int s = 0; s < STAGES - 1; s++) {
        load_part(s, s, 0);
        load_part(s, s, 1);
        load_part(s, s, 2);
        CP_COMMIT();
    }
    CP_WAIT2();              // stage 0 complete
    __syncthreads();
    load_frags(sbase, 0, 0); // (kt=0, ksp=0)

    const int lq = lane >> 2;
    const int lr = lane & 3;

    for (int kt = 0; kt < NKT; kt++) {
        const uint32_t stage = sbase + (uint32_t)(kt % STAGES) * STAGE_B;
        const bool pf   = (kt + STAGES - 1 < NKT);
        const int  pbuf = (kt + STAGES - 1) % STAGES;
        const int  pkt  = kt + STAGES - 1;

        // ksp 0..2: mma + preload next ksp frags + spread next-stage cp.asyncs
        #pragma unroll
        for (int ksp = 0; ksp < 3; ksp++) {
            const int cur = ksp & 1;
            load_frags(stage, ksp + 1, cur ^ 1);
            if (pf) load_part(pbuf, pkt, ksp);
            mma_batch(cur);
        }
        CP_COMMIT();

        if (kt + 1 < NKT) {
            // commits = 4+kt; wait 2 -> stages <= kt+1 complete
            CP_WAIT2();
            __syncthreads();
            // prefetch next kt's ksp0 frags (pb=0) while ksp3 (pb=1) computes
            load_frags(sbase + (uint32_t)((kt + 1) % STAGES) * STAGE_B, 0, 0);
        }
        mma_batch(1);   // ksp3
    }

    // epilogue
    const int crow = bm + warp_m * 64 + lq;
    const int ccol = bn + warp_n * 64 + 2 * lr;
    #pragma unroll
    for (int mt = 0; mt < 4; mt++) {
        #pragma unroll
        for (int nt = 0; nt < 8; nt++) {
            float* p0 = C + (size_t)(crow + mt * 16) * OUT_F + ccol + nt * 8;
            float* p1 = p0 + (size_t)8 * OUT_F;
            *reinterpret_cast<float2*>(p0) = make_float2(acc[mt][nt][0], acc[mt][nt][1]);
            *reinterpret_cast<float2*>(p1) = make_float2(acc[mt][nt][2], acc[mt][nt][3]);
        }
    }
}

// ---------------------------------------------------------------------------
extern "C" void kernel_launch(void* const* d_in, const int* in_sizes, int n_in,
                              void* d_out, int out_size) {
    const float* input   = (const float*)d_in[0];
    const int*   trellis = (const int*)  d_in[1];
    const float* tlut    = (const float*)d_in[2];
    const float* scales  = (const float*)d_in[3];
    float*       out     = (float*)d_out;

    __half* xbuf; __half* wbuf;
    cudaGetSymbolAddress((void**)&xbuf, g_x);
    cudaGetSymbolAddress((void**)&wbuf, g_W);

    prep_kernel<<<PREP_BLOCKS, 256>>>(input, xbuf, trellis, tlut, scales, wbuf);

    static bool attr_set = false;
    if (!attr_set) {
        cudaFuncSetAttribute(gemm_mma_kernel,
                             cudaFuncAttributeMaxDynamicSharedMemorySize, SMEM_TOTAL);
        attr_set = true;
    }
    const int nblocks = (M_TOT / BM) * (OUT_F / BN);   // 1024
    gemm_mma_kernel<<<nblocks, 256, SMEM_TOTAL>>>(xbuf, wbuf, out);
}